// round 1
// baseline (speedup 1.0000x reference)
#include <cuda_runtime.h>
#include <math.h>

// Problem constants
#define BB   4
#define NN   16384
#define WW   256
#define MM   32
#define HH   8
#define DHH  32
#define FFD  1024
#define LL   8
#define BN   (BB*NN)

// Scratch (device globals — allocation-free rule)
__device__ float g_x[BN*WW];        // 64 MB  residual stream
__device__ float g_h[BN*WW];        // 64 MB  LN output (reused for h and h2)
__device__ float g_w[BN*MM];        // 8 MB   slice weights
__device__ float g_u[BN*FFD];       // 256 MB FFN hidden
__device__ float g_z[BB*MM*WW];     // slice tokens
__device__ float g_qkv[BB*MM*3*WW];
__device__ float g_o[BB*MM*WW];
__device__ float g_zp[BB*MM*WW];
__device__ float g_wsum[BB*MM];

typedef unsigned long long ull;

__device__ __forceinline__ void ffma2(ull& d, ull a, ull b){
    asm("fma.rn.f32x2 %0, %1, %2, %0;" : "+l"(d) : "l"(a), "l"(b));
}
__device__ __forceinline__ ull pk2(float lo, float hi){
    ull r; asm("mov.b64 %0, {%1, %2};" : "=l"(r) : "f"(lo), "f"(hi)); return r;
}
__device__ __forceinline__ void upk2(ull v, float& lo, float& hi){
    asm("mov.b64 {%0, %1}, %2;" : "=f"(lo), "=f"(hi) : "l"(v));
}

// ---------------------------------------------------------------------------
// Embedding: x = concat(feat[4], coord[3], temb[8]) @ embed_w(15,256) + b
// ---------------------------------------------------------------------------
__global__ __launch_bounds__(256) void k_embed(
    const float* __restrict__ feat, const float* __restrict__ coord,
    const float* __restrict__ tn,   const float* __restrict__ ew,
    const float* __restrict__ eb)
{
    int row = blockIdx.x;          // 0..BN-1
    int b   = row >> 14;           // N = 16384
    int t   = threadIdx.x;
    __shared__ float in15[16];
    if (t < 4) {
        in15[t] = feat[row*4 + t];
    } else if (t < 7) {
        in15[t] = coord[row*3 + (t-4)];
    } else if (t < 15) {
        int i = (t - 7) & 3;
        float omega = (float)exp(-(double)i * log(1000.0) / 4.0);
        float ang   = omega * (tn[b] * 1000.0f);
        in15[t] = (t < 11) ? sinf(ang) : cosf(ang);
    }
    __syncthreads();
    float acc = eb[t];
    #pragma unroll
    for (int j = 0; j < 15; j++) acc = fmaf(in15[j], ew[j*WW + t], acc);
    g_x[row*WW + t] = acc;
}

// ---------------------------------------------------------------------------
// LayerNorm helper (block of 256 threads = one row)
// ---------------------------------------------------------------------------
__device__ __forceinline__ float ln_row(int row, int t,
    const float* __restrict__ gam, const float* __restrict__ bet, float* red)
{
    float xv = g_x[row*WW + t];
    float s = xv;
    #pragma unroll
    for (int o = 16; o; o >>= 1) s += __shfl_xor_sync(0xffffffffu, s, o);
    if ((t & 31) == 0) red[t >> 5] = s;
    __syncthreads();
    if (t < 8) {
        float r = red[t];
        #pragma unroll
        for (int o = 4; o; o >>= 1) r += __shfl_xor_sync(0xffu, r, o);
        if (t == 0) red[8] = r;
    }
    __syncthreads();
    float mean = red[8] * (1.0f/WW);
    float d = xv - mean;
    float s2 = d*d;
    #pragma unroll
    for (int o = 16; o; o >>= 1) s2 += __shfl_xor_sync(0xffffffffu, s2, o);
    if ((t & 31) == 0) red[t >> 5] = s2;
    __syncthreads();
    if (t < 8) {
        float r = red[t];
        #pragma unroll
        for (int o = 4; o; o >>= 1) r += __shfl_xor_sync(0xffu, r, o);
        if (t == 0) red[9] = r;
    }
    __syncthreads();
    float var = red[9] * (1.0f/WW);
    return d * rsqrtf(var + 1e-5f) * gam[t] + bet[t];
}

// LN1 + slice logits + softmax + wsum atomic
__global__ __launch_bounds__(256) void k_ln_slice(
    const float* __restrict__ gam, const float* __restrict__ bet,
    const float* __restrict__ sw,  const float* __restrict__ sb)
{
    int row = blockIdx.x;
    int b   = row >> 14;
    int t   = threadIdx.x;
    __shared__ float red[16];
    __shared__ float sh[WW];
    __shared__ float part[256];

    float hv = ln_row(row, t, gam, bet, red);
    g_h[row*WW + t] = hv;
    sh[t] = hv;
    __syncthreads();

    int m = t & 31, kb = t >> 5;      // 8 k-blocks of 32
    float p = 0.0f;
    #pragma unroll
    for (int k = 0; k < 32; k++)
        p = fmaf(sh[kb*32 + k], sw[(kb*32 + k)*MM + m], p);
    part[t] = p;
    __syncthreads();

    if (t < 32) {
        float lg = sb[t];
        #pragma unroll
        for (int kb2 = 0; kb2 < 8; kb2++) lg += part[kb2*32 + t];
        float mx = lg;
        #pragma unroll
        for (int o = 16; o; o >>= 1) mx = fmaxf(mx, __shfl_xor_sync(0xffffffffu, mx, o));
        float e = expf(lg - mx);
        float se = e;
        #pragma unroll
        for (int o = 16; o; o >>= 1) se += __shfl_xor_sync(0xffffffffu, se, o);
        float wv = e / se;
        g_w[row*MM + t] = wv;
        atomicAdd(&g_wsum[b*MM + t], wv);
    }
}

// LN2 only (writes g_h)
__global__ __launch_bounds__(256) void k_ln(
    const float* __restrict__ gam, const float* __restrict__ bet)
{
    int row = blockIdx.x;
    int t   = threadIdx.x;
    __shared__ float red[16];
    g_h[row*WW + t] = ln_row(row, t, gam, bet, red);
}

// zero z + wsum
__global__ void k_zero()
{
    int i = blockIdx.x*256 + threadIdx.x;
    if (i < BB*MM*WW) g_z[i] = 0.0f;
    if (i < BB*MM)    g_wsum[i] = 0.0f;
}

// ---------------------------------------------------------------------------
// z[b,m,c] += sum_n w[b,n,m] * h[b,n,c]   (chunked over n, atomics into g_z)
// ---------------------------------------------------------------------------
__global__ __launch_bounds__(256) void k_zacc()
{
    int bx = blockIdx.x;         // 256 blocks: b = bx/64, chunk = bx%64
    int b  = bx >> 6;
    int n0 = (bx & 63) * 256;
    int t  = threadIdx.x;
    __shared__ __align__(8) float shw[8*32];

    ull acc[16];
    #pragma unroll
    for (int i = 0; i < 16; i++) acc[i] = pk2(0.0f, 0.0f);

    for (int nb = 0; nb < 256; nb += 8) {
        int n = n0 + nb + (t >> 5);
        shw[t] = g_w[(b*NN + n)*MM + (t & 31)];
        __syncthreads();
        #pragma unroll
        for (int j = 0; j < 8; j++) {
            float hv = g_h[(b*NN + n0 + nb + j)*WW + t];
            ull hp = pk2(hv, hv);
            const ull* wp = (const ull*)&shw[j*32];
            #pragma unroll
            for (int mp = 0; mp < 16; mp++) ffma2(acc[mp], hp, wp[mp]);
        }
        __syncthreads();
    }
    #pragma unroll
    for (int mp = 0; mp < 16; mp++) {
        float lo, hi; upk2(acc[mp], lo, hi);
        atomicAdd(&g_z[(b*MM + 2*mp    )*WW + t], lo);
        atomicAdd(&g_z[(b*MM + 2*mp + 1)*WW + t], hi);
    }
}

// ---------------------------------------------------------------------------
// small GEMM on 32 tokens: out = in(32x256) @ wt(256 x ncols) + bias
// mode 0: in = g_z / wsum  -> g_qkv ; mode 1: in = g_o -> g_zp
// ---------------------------------------------------------------------------
__global__ __launch_bounds__(256) void k_smallmm(
    const float* __restrict__ wt, const float* __restrict__ bias,
    int ncols, int mode)
{
    int nb = ncols >> 5;
    int b  = blockIdx.x / nb;
    int cb = blockIdx.x % nb;
    int t  = threadIdx.x;
    __shared__ float zs[32*257];

    for (int i = t; i < 32*256; i += 256) {
        int m = i >> 8, c = i & 255;
        float v;
        if (mode == 0) v = g_z[(b*MM + m)*WW + c] / fmaxf(g_wsum[b*MM + m], 1e-8f);
        else           v = g_o[(b*MM + m)*WW + c];
        zs[m*257 + c] = v;
    }
    __syncthreads();

    int r  = t & 31;
    int c0 = cb*32 + (t >> 5)*4;
    float a0 = bias[c0], a1 = bias[c0+1], a2 = bias[c0+2], a3 = bias[c0+3];
    for (int k = 0; k < 256; k++) {
        float zv = zs[r*257 + k];
        const float* wr = &wt[k*ncols + c0];
        a0 = fmaf(zv, wr[0], a0);
        a1 = fmaf(zv, wr[1], a1);
        a2 = fmaf(zv, wr[2], a2);
        a3 = fmaf(zv, wr[3], a3);
    }
    float* outp = (mode == 0) ? &g_qkv[(b*MM + r)*3*WW] : &g_zp[(b*MM + r)*WW];
    outp[c0] = a0; outp[c0+1] = a1; outp[c0+2] = a2; outp[c0+3] = a3;
}

// ---------------------------------------------------------------------------
// attention over M=32 tokens, per (b, head)
// ---------------------------------------------------------------------------
__global__ __launch_bounds__(256) void k_attn()
{
    int b = blockIdx.x >> 3, h = blockIdx.x & 7, t = threadIdx.x;
    __shared__ float qs[32*33], ks[32*33], vs[32*33], ss[32*33];

    for (int i = t; i < 1024; i += 256) {
        int m = i >> 5, d = i & 31;
        int base = (b*MM + m)*3*WW + h*DHH + d;
        qs[m*33 + d] = g_qkv[base];
        ks[m*33 + d] = g_qkv[base + WW];
        vs[m*33 + d] = g_qkv[base + 2*WW];
    }
    __syncthreads();

    int i = t & 31, j0 = (t >> 5)*4;
    float sc[4] = {0,0,0,0};
    #pragma unroll
    for (int d = 0; d < 32; d++) {
        float qv = qs[i*33 + d];
        #pragma unroll
        for (int jj = 0; jj < 4; jj++) sc[jj] = fmaf(qv, ks[(j0+jj)*33 + d], sc[jj]);
    }
    const float scale = 0.17677669529663687f; // 1/sqrt(32)
    #pragma unroll
    for (int jj = 0; jj < 4; jj++) ss[i*33 + j0 + jj] = sc[jj]*scale;
    __syncthreads();

    if (t < 32) {
        float mx = -1e30f;
        for (int j = 0; j < 32; j++) mx = fmaxf(mx, ss[t*33 + j]);
        float se = 0.0f;
        for (int j = 0; j < 32; j++) { float e = expf(ss[t*33 + j] - mx); ss[t*33 + j] = e; se += e; }
        float inv = 1.0f / se;
        for (int j = 0; j < 32; j++) ss[t*33 + j] *= inv;
    }
    __syncthreads();

    int d0 = (t >> 5)*4;
    float oc[4] = {0,0,0,0};
    #pragma unroll
    for (int j = 0; j < 32; j++) {
        float av = ss[i*33 + j];
        #pragma unroll
        for (int dd = 0; dd < 4; dd++) oc[dd] = fmaf(av, vs[j*33 + d0 + dd], oc[dd]);
    }
    #pragma unroll
    for (int dd = 0; dd < 4; dd++) g_o[(b*MM + i)*WW + h*DHH + d0 + dd] = oc[dd];
}

// ---------------------------------------------------------------------------
// scatter back: x[row,:] += sum_m w[row,m] * zp[b,m,:]
// ---------------------------------------------------------------------------
__global__ __launch_bounds__(256) void k_scatter()
{
    int t = threadIdx.x;
    int row0 = blockIdx.x * 16;
    int b = row0 >> 14;
    __shared__ float zps[MM*WW];
    __shared__ float wr[32];

    for (int i = t; i < MM*WW; i += 256) zps[i] = g_zp[b*MM*WW + i];
    __syncthreads();

    for (int r = 0; r < 16; r++) {
        int row = row0 + r;
        if (t < 32) wr[t] = g_w[row*MM + t];
        __syncthreads();
        float acc = g_x[row*WW + t];
        #pragma unroll
        for (int m = 0; m < 32; m++) acc = fmaf(wr[m], zps[m*WW + t], acc);
        g_x[row*WW + t] = acc;
        __syncthreads();
    }
}

// ---------------------------------------------------------------------------
// Tiled fp32 GEMM with packed f32x2 FMA. 128x128x16 tiles, 256 thr, 8x8/thr.
// MODE 0:  g_u = gelu(g_h @ Bw + bias)       (K=256, Ncols=1024)
// MODE 1:  g_x += g_u @ Bw + bias            (K=1024, Ncols=256)
// ---------------------------------------------------------------------------
template<int MODE>
__global__ __launch_bounds__(256, 2) void k_gemm(
    const float* __restrict__ Bw, const float* __restrict__ bias,
    int K, int Ncols)
{
    const float* __restrict__ A = (MODE == 0) ? g_h : g_u;
    float* __restrict__ C       = (MODE == 0) ? g_u : g_x;

    __shared__ __align__(16) float As[16*132];
    __shared__ __align__(16) float Bs[16*128];

    int t   = threadIdx.x;
    int bm0 = blockIdx.y * 128;
    int bn0 = blockIdx.x * 128;
    int tx  = t & 15, ty = t >> 4;
    int m0  = ty*8,  n0 = tx*8;

    ull acc[8][4];
    #pragma unroll
    for (int i = 0; i < 8; i++)
        #pragma unroll
        for (int j = 0; j < 4; j++) acc[i][j] = pk2(0.0f, 0.0f);

    for (int k0 = 0; k0 < K; k0 += 16) {
        #pragma unroll
        for (int i = 0; i < 2; i++) {
            int idx = t*2 + i;
            int ar = idx >> 2, kq = idx & 3;
            float4 v = *(const float4*)&A[(size_t)(bm0 + ar)*K + k0 + kq*4];
            As[(kq*4 + 0)*132 + ar] = v.x;
            As[(kq*4 + 1)*132 + ar] = v.y;
            As[(kq*4 + 2)*132 + ar] = v.z;
            As[(kq*4 + 3)*132 + ar] = v.w;
        }
        #pragma unroll
        for (int i = 0; i < 2; i++) {
            int idx = t*2 + i;
            int kr = idx >> 5, cq = idx & 31;
            *(float4*)&Bs[kr*128 + cq*4] =
                *(const float4*)&Bw[(size_t)(k0 + kr)*Ncols + bn0 + cq*4];
        }
        __syncthreads();

        #pragma unroll
        for (int k = 0; k < 16; k++) {
            float4 a0 = *(float4*)&As[k*132 + m0];
            float4 a1 = *(float4*)&As[k*132 + m0 + 4];
            float4 b0 = *(float4*)&Bs[k*128 + n0];
            float4 b1 = *(float4*)&Bs[k*128 + n0 + 4];
            ull bp[4];
            bp[0] = pk2(b0.x, b0.y); bp[1] = pk2(b0.z, b0.w);
            bp[2] = pk2(b1.x, b1.y); bp[3] = pk2(b1.z, b1.w);
            ull ap[8];
            ap[0] = pk2(a0.x, a0.x); ap[1] = pk2(a0.y, a0.y);
            ap[2] = pk2(a0.z, a0.z); ap[3] = pk2(a0.w, a0.w);
            ap[4] = pk2(a1.x, a1.x); ap[5] = pk2(a1.y, a1.y);
            ap[6] = pk2(a1.z, a1.z); ap[7] = pk2(a1.w, a1.w);
            #pragma unroll
            for (int i = 0; i < 8; i++)
                #pragma unroll
                for (int j = 0; j < 4; j++) ffma2(acc[i][j], ap[i], bp[j]);
        }
        __syncthreads();
    }

    #pragma unroll
    for (int i = 0; i < 8; i++) {
        size_t row = bm0 + m0 + i;
        float out[8];
        #pragma unroll
        for (int j = 0; j < 4; j++) upk2(acc[i][j], out[2*j], out[2*j+1]);
        #pragma unroll
        for (int j = 0; j < 8; j++) {
            int col = bn0 + n0 + j;
            float v = out[j] + bias[col];
            if (MODE == 0) {
                out[j] = 0.5f * v * (1.0f + erff(v * 0.7071067811865476f));
            } else {
                out[j] = v + C[row*Ncols + col];
            }
        }
        *(float4*)&C[row*Ncols + bn0 + n0]     = make_float4(out[0], out[1], out[2], out[3]);
        *(float4*)&C[row*Ncols + bn0 + n0 + 4] = make_float4(out[4], out[5], out[6], out[7]);
    }
}

// ---------------------------------------------------------------------------
// final projection: out = x @ proj_w(256,4) + proj_b
// ---------------------------------------------------------------------------
__global__ __launch_bounds__(256) void k_proj(
    const float* __restrict__ pw, const float* __restrict__ pb,
    float* __restrict__ out)
{
    int t = threadIdx.x;
    int warp = t >> 5, lane = t & 31;
    int row = blockIdx.x*8 + warp;
    float a[4] = {0,0,0,0};
    for (int k = lane; k < 256; k += 32) {
        float xv = g_x[row*WW + k];
        #pragma unroll
        for (int c = 0; c < 4; c++) a[c] = fmaf(xv, pw[k*4 + c], a[c]);
    }
    #pragma unroll
    for (int c = 0; c < 4; c++)
        #pragma unroll
        for (int o = 16; o; o >>= 1) a[c] += __shfl_xor_sync(0xffffffffu, a[c], o);
    if (lane < 4) out[row*4 + lane] = a[lane] + pb[lane];
}

// ---------------------------------------------------------------------------
extern "C" void kernel_launch(void* const* d_in, const int* in_sizes, int n_in,
                              void* d_out, int out_size)
{
    const float* feat  = (const float*)d_in[0];
    const float* coord = (const float*)d_in[1];
    const float* tn    = (const float*)d_in[2];
    const float* ew    = (const float*)d_in[3];
    const float* eb    = (const float*)d_in[4];
    const float* ln1g  = (const float*)d_in[5];
    const float* ln1b  = (const float*)d_in[6];
    const float* sw    = (const float*)d_in[7];
    const float* sb    = (const float*)d_in[8];
    const float* qkvw  = (const float*)d_in[9];
    const float* qkvb  = (const float*)d_in[10];
    const float* outw  = (const float*)d_in[11];
    const float* outb  = (const float*)d_in[12];
    const float* ln2g  = (const float*)d_in[13];
    const float* ln2b  = (const float*)d_in[14];
    const float* f1w   = (const float*)d_in[15];
    const float* f1b   = (const float*)d_in[16];
    const float* f2w   = (const float*)d_in[17];
    const float* f2b   = (const float*)d_in[18];
    const float* pw    = (const float*)d_in[19];
    const float* pb    = (const float*)d_in[20];

    k_embed<<<BN, 256>>>(feat, coord, tn, ew, eb);

    for (int l = 0; l < LL; l++) {
        k_zero<<<128, 256>>>();
        k_ln_slice<<<BN, 256>>>(ln1g + l*WW, ln1b + l*WW,
                                sw + (size_t)l*WW*MM, sb + l*MM);
        k_zacc<<<256, 256>>>();
        k_smallmm<<<BB*24, 256>>>(qkvw + (size_t)l*WW*3*WW, qkvb + l*3*WW, 3*WW, 0);
        k_attn<<<BB*HH, 256>>>();
        k_smallmm<<<BB*8, 256>>>(outw + (size_t)l*WW*WW, outb + l*WW, WW, 1);
        k_scatter<<<BN/16, 256>>>();
        k_ln<<<BN, 256>>>(ln2g + l*WW, ln2b + l*WW);
        {
            dim3 g1(FFD/128, BN/128);   // 8 x 512
            k_gemm<0><<<g1, 256>>>(f1w + (size_t)l*WW*FFD, f1b + l*FFD, WW, FFD);
            dim3 g2(WW/128, BN/128);    // 2 x 512
            k_gemm<1><<<g2, 256>>>(f2w + (size_t)l*FFD*WW, f2b + l*WW, FFD, WW);
        }
    }

    k_proj<<<BN/8, 256>>>(pw, pb, (float*)d_out);
}

// round 3
// speedup vs baseline: 1.5561x; 1.5561x over previous
#include <cuda_runtime.h>
#include <math.h>

// Problem constants
#define BB   4
#define NN   16384
#define WW   256
#define MM   32
#define HH   8
#define DHH  32
#define FFD  1024
#define LL   8
#define BN   (BB*NN)

// Scratch (device globals — allocation-free rule)
__device__ float g_x[BN*WW];        // 64 MB  residual stream
__device__ float g_h[BN*WW];        // 64 MB  LN output (reused for h and h2)
__device__ float g_w[BN*MM];        // 8 MB   slice weights
__device__ float g_u[BN*FFD];       // 256 MB FFN hidden
__device__ float g_z[BB*MM*WW];     // slice tokens
__device__ float g_qkv[BB*MM*3*WW];
__device__ float g_o[BB*MM*WW];
__device__ float g_zp[BB*MM*WW];
__device__ float g_wsum[BB*MM];

typedef unsigned long long ull;

__device__ __forceinline__ void ffma2(ull& d, ull a, ull b){
    asm("fma.rn.f32x2 %0, %1, %2, %0;" : "+l"(d) : "l"(a), "l"(b));
}
__device__ __forceinline__ ull pk2(float lo, float hi){
    ull r; asm("mov.b64 %0, {%1, %2};" : "=l"(r) : "f"(lo), "f"(hi)); return r;
}
__device__ __forceinline__ void upk2(ull v, float& lo, float& hi){
    asm("mov.b64 {%0, %1}, %2;" : "=f"(lo), "=f"(hi) : "l"(v));
}
__device__ __forceinline__ unsigned cvt_tf32(float f){
    unsigned r; asm("cvt.rna.tf32.f32 %0, %1;" : "=r"(r) : "f"(f)); return r;
}

// ---------------------------------------------------------------------------
// Embedding: x = concat(feat[4], coord[3], temb[8]) @ embed_w(15,256) + b
// ---------------------------------------------------------------------------
__global__ __launch_bounds__(256) void k_embed(
    const float* __restrict__ feat, const float* __restrict__ coord,
    const float* __restrict__ tn,   const float* __restrict__ ew,
    const float* __restrict__ eb)
{
    int row = blockIdx.x;          // 0..BN-1
    int b   = row >> 14;           // N = 16384
    int t   = threadIdx.x;
    __shared__ float in15[16];
    if (t < 4) {
        in15[t] = feat[row*4 + t];
    } else if (t < 7) {
        in15[t] = coord[row*3 + (t-4)];
    } else if (t < 15) {
        int i = (t - 7) & 3;
        float omega = (float)exp(-(double)i * log(1000.0) / 4.0);
        float ang   = omega * (tn[b] * 1000.0f);
        in15[t] = (t < 11) ? sinf(ang) : cosf(ang);
    }
    __syncthreads();
    float acc = eb[t];
    #pragma unroll
    for (int j = 0; j < 15; j++) acc = fmaf(in15[j], ew[j*WW + t], acc);
    g_x[row*WW + t] = acc;
}

// ---------------------------------------------------------------------------
// LayerNorm helper (block of 256 threads = one row)
// ---------------------------------------------------------------------------
__device__ __forceinline__ float ln_row(int row, int t,
    const float* __restrict__ gam, const float* __restrict__ bet, float* red)
{
    float xv = g_x[row*WW + t];
    float s = xv;
    #pragma unroll
    for (int o = 16; o; o >>= 1) s += __shfl_xor_sync(0xffffffffu, s, o);
    if ((t & 31) == 0) red[t >> 5] = s;
    __syncthreads();
    if (t < 8) {
        float r = red[t];
        #pragma unroll
        for (int o = 4; o; o >>= 1) r += __shfl_xor_sync(0xffu, r, o);
        if (t == 0) red[8] = r;
    }
    __syncthreads();
    float mean = red[8] * (1.0f/WW);
    float d = xv - mean;
    float s2 = d*d;
    #pragma unroll
    for (int o = 16; o; o >>= 1) s2 += __shfl_xor_sync(0xffffffffu, s2, o);
    if ((t & 31) == 0) red[t >> 5] = s2;
    __syncthreads();
    if (t < 8) {
        float r = red[t];
        #pragma unroll
        for (int o = 4; o; o >>= 1) r += __shfl_xor_sync(0xffu, r, o);
        if (t == 0) red[9] = r;
    }
    __syncthreads();
    float var = red[9] * (1.0f/WW);
    return d * rsqrtf(var + 1e-5f) * gam[t] + bet[t];
}

// LN1 + slice logits + softmax + wsum atomic
__global__ __launch_bounds__(256) void k_ln_slice(
    const float* __restrict__ gam, const float* __restrict__ bet,
    const float* __restrict__ sw,  const float* __restrict__ sb)
{
    int row = blockIdx.x;
    int b   = row >> 14;
    int t   = threadIdx.x;
    __shared__ float red[16];
    __shared__ float sh[WW];
    __shared__ float part[256];

    float hv = ln_row(row, t, gam, bet, red);
    g_h[row*WW + t] = hv;
    sh[t] = hv;
    __syncthreads();

    int m = t & 31, kb = t >> 5;      // 8 k-blocks of 32
    float p = 0.0f;
    #pragma unroll
    for (int k = 0; k < 32; k++)
        p = fmaf(sh[kb*32 + k], sw[(kb*32 + k)*MM + m], p);
    part[t] = p;
    __syncthreads();

    if (t < 32) {
        float lg = sb[t];
        #pragma unroll
        for (int kb2 = 0; kb2 < 8; kb2++) lg += part[kb2*32 + t];
        float mx = lg;
        #pragma unroll
        for (int o = 16; o; o >>= 1) mx = fmaxf(mx, __shfl_xor_sync(0xffffffffu, mx, o));
        float e = expf(lg - mx);
        float se = e;
        #pragma unroll
        for (int o = 16; o; o >>= 1) se += __shfl_xor_sync(0xffffffffu, se, o);
        float wv = e / se;
        g_w[row*MM + t] = wv;
        atomicAdd(&g_wsum[b*MM + t], wv);
    }
}

// LN2 only (writes g_h)
__global__ __launch_bounds__(256) void k_ln(
    const float* __restrict__ gam, const float* __restrict__ bet)
{
    int row = blockIdx.x;
    int t   = threadIdx.x;
    __shared__ float red[16];
    g_h[row*WW + t] = ln_row(row, t, gam, bet, red);
}

// zero z + wsum
__global__ void k_zero()
{
    int i = blockIdx.x*256 + threadIdx.x;
    if (i < BB*MM*WW) g_z[i] = 0.0f;
    if (i < BB*MM)    g_wsum[i] = 0.0f;
}

// ---------------------------------------------------------------------------
// z[b,m,c] += sum_n w[b,n,m] * h[b,n,c]   (chunked over n, atomics into g_z)
// 1024 blocks x 64 rows each
// ---------------------------------------------------------------------------
__global__ __launch_bounds__(256) void k_zacc()
{
    int bx = blockIdx.x;         // 1024 blocks: b = bx/256, chunk = bx%256
    int b  = bx >> 8;
    int n0 = (bx & 255) * 64;
    int t  = threadIdx.x;
    __shared__ __align__(8) float shw[8*32];

    ull acc[16];
    #pragma unroll
    for (int i = 0; i < 16; i++) acc[i] = pk2(0.0f, 0.0f);

    for (int nb = 0; nb < 64; nb += 8) {
        int n = n0 + nb + (t >> 5);
        shw[t] = g_w[(b*NN + n)*MM + (t & 31)];
        __syncthreads();
        #pragma unroll
        for (int j = 0; j < 8; j++) {
            float hv = g_h[(b*NN + n0 + nb + j)*WW + t];
            ull hp = pk2(hv, hv);
            const ull* wp = (const ull*)&shw[j*32];
            #pragma unroll
            for (int mp = 0; mp < 16; mp++) ffma2(acc[mp], hp, wp[mp]);
        }
        __syncthreads();
    }
    #pragma unroll
    for (int mp = 0; mp < 16; mp++) {
        float lo, hi; upk2(acc[mp], lo, hi);
        atomicAdd(&g_z[(b*MM + 2*mp    )*WW + t], lo);
        atomicAdd(&g_z[(b*MM + 2*mp + 1)*WW + t], hi);
    }
}

// ---------------------------------------------------------------------------
// small GEMM on 32 tokens: out = in(32x256) @ wt(256 x ncols) + bias
// mode 0: in = g_z / wsum  -> g_qkv ; mode 1: in = g_o -> g_zp
// ---------------------------------------------------------------------------
__global__ __launch_bounds__(256) void k_smallmm(
    const float* __restrict__ wt, const float* __restrict__ bias,
    int ncols, int mode)
{
    int nb = ncols >> 5;
    int b  = blockIdx.x / nb;
    int cb = blockIdx.x % nb;
    int t  = threadIdx.x;
    __shared__ float zs[32*257];

    for (int i = t; i < 32*256; i += 256) {
        int m = i >> 8, c = i & 255;
        float v;
        if (mode == 0) v = g_z[(b*MM + m)*WW + c] / fmaxf(g_wsum[b*MM + m], 1e-8f);
        else           v = g_o[(b*MM + m)*WW + c];
        zs[m*257 + c] = v;
    }
    __syncthreads();

    int r  = t & 31;
    int c0 = cb*32 + (t >> 5)*4;
    float a0 = bias[c0], a1 = bias[c0+1], a2 = bias[c0+2], a3 = bias[c0+3];
    for (int k = 0; k < 256; k++) {
        float zv = zs[r*257 + k];
        const float* wr = &wt[k*ncols + c0];
        a0 = fmaf(zv, wr[0], a0);
        a1 = fmaf(zv, wr[1], a1);
        a2 = fmaf(zv, wr[2], a2);
        a3 = fmaf(zv, wr[3], a3);
    }
    float* outp = (mode == 0) ? &g_qkv[(b*MM + r)*3*WW] : &g_zp[(b*MM + r)*WW];
    outp[c0] = a0; outp[c0+1] = a1; outp[c0+2] = a2; outp[c0+3] = a3;
}

// ---------------------------------------------------------------------------
// attention over M=32 tokens, per (b, head)
// ---------------------------------------------------------------------------
__global__ __launch_bounds__(256) void k_attn()
{
    int b = blockIdx.x >> 3, h = blockIdx.x & 7, t = threadIdx.x;
    __shared__ float qs[32*33], ks[32*33], vs[32*33], ss[32*33];

    for (int i = t; i < 1024; i += 256) {
        int m = i >> 5, d = i & 31;
        int base = (b*MM + m)*3*WW + h*DHH + d;
        qs[m*33 + d] = g_qkv[base];
        ks[m*33 + d] = g_qkv[base + WW];
        vs[m*33 + d] = g_qkv[base + 2*WW];
    }
    __syncthreads();

    int i = t & 31, j0 = (t >> 5)*4;
    float sc[4] = {0,0,0,0};
    #pragma unroll
    for (int d = 0; d < 32; d++) {
        float qv = qs[i*33 + d];
        #pragma unroll
        for (int jj = 0; jj < 4; jj++) sc[jj] = fmaf(qv, ks[(j0+jj)*33 + d], sc[jj]);
    }
    const float scale = 0.17677669529663687f; // 1/sqrt(32)
    #pragma unroll
    for (int jj = 0; jj < 4; jj++) ss[i*33 + j0 + jj] = sc[jj]*scale;
    __syncthreads();

    if (t < 32) {
        float mx = -1e30f;
        for (int j = 0; j < 32; j++) mx = fmaxf(mx, ss[t*33 + j]);
        float se = 0.0f;
        for (int j = 0; j < 32; j++) { float e = expf(ss[t*33 + j] - mx); ss[t*33 + j] = e; se += e; }
        float inv = 1.0f / se;
        for (int j = 0; j < 32; j++) ss[t*33 + j] *= inv;
    }
    __syncthreads();

    int d0 = (t >> 5)*4;
    float oc[4] = {0,0,0,0};
    #pragma unroll
    for (int j = 0; j < 32; j++) {
        float av = ss[i*33 + j];
        #pragma unroll
        for (int dd = 0; dd < 4; dd++) oc[dd] = fmaf(av, vs[j*33 + d0 + dd], oc[dd]);
    }
    #pragma unroll
    for (int dd = 0; dd < 4; dd++) g_o[(b*MM + i)*WW + h*DHH + d0 + dd] = oc[dd];
}

// ---------------------------------------------------------------------------
// scatter back: x[row,:] += sum_m w[row,m] * zp[b,m,:]
// ---------------------------------------------------------------------------
__global__ __launch_bounds__(256) void k_scatter()
{
    int t = threadIdx.x;
    int row0 = blockIdx.x * 16;
    int b = row0 >> 14;
    __shared__ float zps[MM*WW];
    __shared__ float wr[32];

    for (int i = t; i < MM*WW; i += 256) zps[i] = g_zp[b*MM*WW + i];
    __syncthreads();

    for (int r = 0; r < 16; r++) {
        int row = row0 + r;
        if (t < 32) wr[t] = g_w[row*MM + t];
        __syncthreads();
        float acc = g_x[row*WW + t];
        #pragma unroll
        for (int m = 0; m < 32; m++) acc = fmaf(wr[m], zps[m*WW + t], acc);
        g_x[row*WW + t] = acc;
        __syncthreads();
    }
}

// ---------------------------------------------------------------------------
// TF32 tensor-core GEMM (mma.sync.m16n8k8). 128x128 CTA tile, BK=16,
// double-buffered smem, 8 warps @ 64x32 warp tiles.
// MODE 0:  g_u = gelu(g_h @ Bw + bias)       (K=256, Ncols=1024)
// MODE 1:  g_x += g_u @ Bw + bias            (K=1024, Ncols=256)
//
// smem layout: k-columns within each 8-group stored in order [0,4,1,5,2,6,3,7]
// so each thread's mma fragment (k=c and k=c+4) is one 8-byte LDS.
// Row stride 18 words keeps 8B alignment and staggers banks.
// ---------------------------------------------------------------------------
template<int MODE>
__global__ __launch_bounds__(256, 2) void k_gemm_tc(
    const float* __restrict__ Bw, const float* __restrict__ bias,
    int K, int Ncols)
{
    const float* __restrict__ A = (MODE == 0) ? g_h : g_u;
    float* __restrict__ C       = (MODE == 0) ? g_u : g_x;

    __shared__ unsigned As[2][128*18];
    __shared__ unsigned Bs[2][128*18];

    int tid  = threadIdx.x;
    int bm0  = blockIdx.y * 128;
    int bn0  = blockIdx.x * 128;
    int lane = tid & 31, warp = tid >> 5;
    int wm = warp >> 2, wn = warp & 3;      // 2 x 4 warp grid
    int r  = lane >> 2, cc = lane & 3;

    float4 aReg[2], bReg[2];

    float acc[4][4][4];
    #pragma unroll
    for (int mi = 0; mi < 4; mi++)
        #pragma unroll
        for (int ni = 0; ni < 4; ni++)
            #pragma unroll
            for (int e = 0; e < 4; e++) acc[mi][ni][e] = 0.0f;

    // ---- stage load to regs ----
    #define LOAD_STAGE(k0)                                                        \
        _Pragma("unroll")                                                         \
        for (int i = 0; i < 2; i++) {                                             \
            int idx = tid + 256*i;                                                \
            aReg[i] = *(const float4*)&A[(size_t)(bm0 + (idx>>2))*K + (k0) + (idx&3)*4]; \
            bReg[i] = *(const float4*)&Bw[(size_t)((k0) + (idx>>5))*Ncols + bn0 + (idx&31)*4]; \
        }

    // ---- regs -> smem with tf32 convert + k-permute ----
    #define STORE_STAGE(buf)                                                      \
        _Pragma("unroll")                                                         \
        for (int i = 0; i < 2; i++) {                                             \
            int idx = tid + 256*i;                                                \
            int row = idx >> 2, qc = idx & 3;                                     \
            int abase = row*18 + (qc>>1)*8 + (qc&1);                              \
            float av[4] = {aReg[i].x, aReg[i].y, aReg[i].z, aReg[i].w};           \
            _Pragma("unroll")                                                     \
            for (int e = 0; e < 4; e++) As[buf][abase + 2*e] = cvt_tf32(av[e]);   \
            int kk = idx >> 5, nq = idx & 31;                                     \
            int w8 = kk & 7;                                                      \
            int pcol = (kk>>3)*8 + ((w8&3)<<1) + (w8>>2);                         \
            float bv[4] = {bReg[i].x, bReg[i].y, bReg[i].z, bReg[i].w};           \
            _Pragma("unroll")                                                     \
            for (int e = 0; e < 4; e++) Bs[buf][(nq*4+e)*18 + pcol] = cvt_tf32(bv[e]); \
        }

    LOAD_STAGE(0);
    STORE_STAGE(0);
    __syncthreads();

    int nStages = K >> 4;
    for (int s = 0; s < nStages; s++) {
        if (s + 1 < nStages) { LOAD_STAGE((s+1) << 4); }
        int buf = s & 1;
        #pragma unroll
        for (int ks = 0; ks < 2; ks++) {
            uint2 af[4][2];
            #pragma unroll
            for (int mi = 0; mi < 4; mi++) {
                int mb = wm*64 + mi*16;
                af[mi][0] = *(const uint2*)&As[buf][(mb + r    )*18 + ks*8 + 2*cc];
                af[mi][1] = *(const uint2*)&As[buf][(mb + r + 8)*18 + ks*8 + 2*cc];
            }
            uint2 bf[4];
            #pragma unroll
            for (int ni = 0; ni < 4; ni++) {
                int nb = wn*32 + ni*8 + r;
                bf[ni] = *(const uint2*)&Bs[buf][nb*18 + ks*8 + 2*cc];
            }
            #pragma unroll
            for (int mi = 0; mi < 4; mi++)
                #pragma unroll
                for (int ni = 0; ni < 4; ni++) {
                    asm volatile(
                        "mma.sync.aligned.m16n8k8.row.col.f32.tf32.tf32.f32 "
                        "{%0,%1,%2,%3}, {%4,%5,%6,%7}, {%8,%9}, {%0,%1,%2,%3};"
                        : "+f"(acc[mi][ni][0]), "+f"(acc[mi][ni][1]),
                          "+f"(acc[mi][ni][2]), "+f"(acc[mi][ni][3])
                        : "r"(af[mi][0].x), "r"(af[mi][1].x),
                          "r"(af[mi][0].y), "r"(af[mi][1].y),
                          "r"(bf[ni].x),    "r"(bf[ni].y));
                }
        }
        if (s + 1 < nStages) { STORE_STAGE((s+1) & 1); }
        __syncthreads();
    }

    // ---- epilogue ----
    #pragma unroll
    for (int mi = 0; mi < 4; mi++) {
        #pragma unroll
        for (int ni = 0; ni < 4; ni++) {
            int col  = bn0 + wn*32 + ni*8 + 2*cc;
            int row0 = bm0 + wm*64 + mi*16 + r;
            float b0v = bias[col], b1v = bias[col+1];
            float v[4];
            v[0] = acc[mi][ni][0] + b0v;  v[1] = acc[mi][ni][1] + b1v;
            v[2] = acc[mi][ni][2] + b0v;  v[3] = acc[mi][ni][3] + b1v;
            if (MODE == 0) {
                #pragma unroll
                for (int e = 0; e < 4; e++)
                    v[e] = 0.5f * v[e] * (1.0f + erff(v[e] * 0.7071067811865476f));
            } else {
                float2 o0 = *(const float2*)&C[(size_t)row0*Ncols + col];
                float2 o1 = *(const float2*)&C[(size_t)(row0+8)*Ncols + col];
                v[0] += o0.x; v[1] += o0.y; v[2] += o1.x; v[3] += o1.y;
            }
            *(float2*)&C[(size_t)row0*Ncols + col]     = make_float2(v[0], v[1]);
            *(float2*)&C[(size_t)(row0+8)*Ncols + col] = make_float2(v[2], v[3]);
        }
    }
}

// ---------------------------------------------------------------------------
// final projection: out = x @ proj_w(256,4) + proj_b
// ---------------------------------------------------------------------------
__global__ __launch_bounds__(256) void k_proj(
    const float* __restrict__ pw, const float* __restrict__ pb,
    float* __restrict__ out)
{
    int t = threadIdx.x;
    int warp = t >> 5, lane = t & 31;
    int row = blockIdx.x*8 + warp;
    float a[4] = {0,0,0,0};
    for (int k = lane; k < 256; k += 32) {
        float xv = g_x[row*WW + k];
        #pragma unroll
        for (int c = 0; c < 4; c++) a[c] = fmaf(xv, pw[k*4 + c], a[c]);
    }
    #pragma unroll
    for (int c = 0; c < 4; c++)
        #pragma unroll
        for (int o = 16; o; o >>= 1) a[c] += __shfl_xor_sync(0xffffffffu, a[c], o);
    if (lane < 4) out[row*4 + lane] = a[lane] + pb[lane];
}

// ---------------------------------------------------------------------------
extern "C" void kernel_launch(void* const* d_in, const int* in_sizes, int n_in,
                              void* d_out, int out_size)
{
    const float* feat  = (const float*)d_in[0];
    const float* coord = (const float*)d_in[1];
    const float* tn    = (const float*)d_in[2];
    const float* ew    = (const float*)d_in[3];
    const float* eb    = (const float*)d_in[4];
    const float* ln1g  = (const float*)d_in[5];
    const float* ln1b  = (const float*)d_in[6];
    const float* sw    = (const float*)d_in[7];
    const float* sb    = (const float*)d_in[8];
    const float* qkvw  = (const float*)d_in[9];
    const float* qkvb  = (const float*)d_in[10];
    const float* outw  = (const float*)d_in[11];
    const float* outb  = (const float*)d_in[12];
    const float* ln2g  = (const float*)d_in[13];
    const float* ln2b  = (const float*)d_in[14];
    const float* f1w   = (const float*)d_in[15];
    const float* f1b   = (const float*)d_in[16];
    const float* f2w   = (const float*)d_in[17];
    const float* f2b   = (const float*)d_in[18];
    const float* pw    = (const float*)d_in[19];
    const float* pb    = (const float*)d_in[20];

    k_embed<<<BN, 256>>>(feat, coord, tn, ew, eb);

    for (int l = 0; l < LL; l++) {
        k_zero<<<128, 256>>>();
        k_ln_slice<<<BN, 256>>>(ln1g + l*WW, ln1b + l*WW,
                                sw + (size_t)l*WW*MM, sb + l*MM);
        k_zacc<<<1024, 256>>>();
        k_smallmm<<<BB*24, 256>>>(qkvw + (size_t)l*WW*3*WW, qkvb + l*3*WW, 3*WW, 0);
        k_attn<<<BB*HH, 256>>>();
        k_smallmm<<<BB*8, 256>>>(outw + (size_t)l*WW*WW, outb + l*WW, WW, 1);
        k_scatter<<<BN/16, 256>>>();
        k_ln<<<BN, 256>>>(ln2g + l*WW, ln2b + l*WW);
        {
            dim3 g1(FFD/128, BN/128);   // 8 x 512
            k_gemm_tc<0><<<g1, 256>>>(f1w + (size_t)l*WW*FFD, f1b + l*FFD, WW, FFD);
            dim3 g2(WW/128, BN/128);    // 2 x 512
            k_gemm_tc<1><<<g2, 256>>>(f2w + (size_t)l*FFD*WW, f2b + l*WW, FFD, WW);
        }
    }

    k_proj<<<BN/8, 256>>>(pw, pb, (float*)d_out);
}

// round 7
// speedup vs baseline: 2.2185x; 1.4257x over previous
#include <cuda_runtime.h>
#include <cuda_fp16.h>
#include <math.h>
#include <stdint.h>

// Problem constants
#define BB   4
#define NN   16384
#define WW   256
#define MM   32
#define HH   8
#define DHH  32
#define FFD  1024
#define LL   8
#define BN   (BB*NN)

// Scratch (device globals — allocation-free rule)
__device__ float g_x[BN*WW];        // residual stream
__device__ float g_h[BN*WW];        // LN output
__device__ float g_w[BN*MM];        // slice weights
__device__ float g_u[BN*FFD];       // FFN hidden
__device__ float g_z[BB*MM*WW];
__device__ float g_qkv[BB*MM*3*WW];
__device__ float g_o[BB*MM*WW];
__device__ float g_zp[BB*MM*WW];
__device__ float g_wsum[BB*MM];
// transposed fp16 weights: [N, K] K-major
__device__ __half g_wB1[LL*FFD*WW];   // ffn1^T : [1024, 256] per layer
__device__ __half g_wB2[LL*WW*FFD];   // ffn2^T : [256, 1024] per layer

typedef unsigned long long ull;

__device__ __forceinline__ void ffma2(ull& d, ull a, ull b){
    asm("fma.rn.f32x2 %0, %1, %2, %0;" : "+l"(d) : "l"(a), "l"(b));
}
__device__ __forceinline__ ull pk2(float lo, float hi){
    ull r; asm("mov.b64 %0, {%1, %2};" : "=l"(r) : "f"(lo), "f"(hi)); return r;
}
__device__ __forceinline__ void upk2(ull v, float& lo, float& hi){
    asm("mov.b64 {%0, %1}, %2;" : "=f"(lo), "=f"(hi) : "l"(v));
}
__device__ __forceinline__ unsigned h2bits(float x, float y){
    __half2 h = __floats2half2_rn(x, y);   // low half = x (lower k), high = y
    return *(unsigned*)&h;
}

// ---------------------------------------------------------------------------
// Embedding: x = concat(feat[4], coord[3], temb[8]) @ embed_w(15,256) + b
// ---------------------------------------------------------------------------
__global__ __launch_bounds__(256) void k_embed(
    const float* __restrict__ feat, const float* __restrict__ coord,
    const float* __restrict__ tn,   const float* __restrict__ ew,
    const float* __restrict__ eb)
{
    int row = blockIdx.x;          // 0..BN-1
    int b   = row >> 14;           // N = 16384
    int t   = threadIdx.x;
    __shared__ float in15[16];
    if (t < 4) {
        in15[t] = feat[row*4 + t];
    } else if (t < 7) {
        in15[t] = coord[row*3 + (t-4)];
    } else if (t < 15) {
        int i = (t - 7) & 3;
        float omega = (float)exp(-(double)i * log(1000.0) / 4.0);
        float ang   = omega * (tn[b] * 1000.0f);
        in15[t] = (t < 11) ? sinf(ang) : cosf(ang);
    }
    __syncthreads();
    float acc = eb[t];
    #pragma unroll
    for (int j = 0; j < 15; j++) acc = fmaf(in15[j], ew[j*WW + t], acc);
    g_x[row*WW + t] = acc;
}

// ---------------------------------------------------------------------------
// LayerNorm helper (block of 256 threads = one row)
// ---------------------------------------------------------------------------
__device__ __forceinline__ float ln_row(int row, int t,
    const float* __restrict__ gam, const float* __restrict__ bet, float* red)
{
    float xv = g_x[row*WW + t];
    float s = xv;
    #pragma unroll
    for (int o = 16; o; o >>= 1) s += __shfl_xor_sync(0xffffffffu, s, o);
    if ((t & 31) == 0) red[t >> 5] = s;
    __syncthreads();
    if (t < 8) {
        float r = red[t];
        #pragma unroll
        for (int o = 4; o; o >>= 1) r += __shfl_xor_sync(0xffu, r, o);
        if (t == 0) red[8] = r;
    }
    __syncthreads();
    float mean = red[8] * (1.0f/WW);
    float d = xv - mean;
    float s2 = d*d;
    #pragma unroll
    for (int o = 16; o; o >>= 1) s2 += __shfl_xor_sync(0xffffffffu, s2, o);
    if ((t & 31) == 0) red[t >> 5] = s2;
    __syncthreads();
    if (t < 8) {
        float r = red[t];
        #pragma unroll
        for (int o = 4; o; o >>= 1) r += __shfl_xor_sync(0xffu, r, o);
        if (t == 0) red[9] = r;
    }
    __syncthreads();
    float var = red[9] * (1.0f/WW);
    return d * rsqrtf(var + 1e-5f) * gam[t] + bet[t];
}

// LN1 + slice logits + softmax + wsum atomic
__global__ __launch_bounds__(256) void k_ln_slice(
    const float* __restrict__ gam, const float* __restrict__ bet,
    const float* __restrict__ sw,  const float* __restrict__ sb)
{
    int row = blockIdx.x;
    int b   = row >> 14;
    int t   = threadIdx.x;
    __shared__ float red[16];
    __shared__ float sh[WW];
    __shared__ float part[256];

    float hv = ln_row(row, t, gam, bet, red);
    g_h[row*WW + t] = hv;
    sh[t] = hv;
    __syncthreads();

    int m = t & 31, kb = t >> 5;
    float p = 0.0f;
    #pragma unroll
    for (int k = 0; k < 32; k++)
        p = fmaf(sh[kb*32 + k], sw[(kb*32 + k)*MM + m], p);
    part[t] = p;
    __syncthreads();

    if (t < 32) {
        float lg = sb[t];
        #pragma unroll
        for (int kb2 = 0; kb2 < 8; kb2++) lg += part[kb2*32 + t];
        float mx = lg;
        #pragma unroll
        for (int o = 16; o; o >>= 1) mx = fmaxf(mx, __shfl_xor_sync(0xffffffffu, mx, o));
        float e = expf(lg - mx);
        float se = e;
        #pragma unroll
        for (int o = 16; o; o >>= 1) se += __shfl_xor_sync(0xffffffffu, se, o);
        float wv = e / se;
        g_w[row*MM + t] = wv;
        atomicAdd(&g_wsum[b*MM + t], wv);
    }
}

// LN2 only (writes g_h)
__global__ __launch_bounds__(256) void k_ln(
    const float* __restrict__ gam, const float* __restrict__ bet)
{
    int row = blockIdx.x;
    int t   = threadIdx.x;
    __shared__ float red[16];
    g_h[row*WW + t] = ln_row(row, t, gam, bet, red);
}

// zero z + wsum
__global__ void k_zero()
{
    int i = blockIdx.x*256 + threadIdx.x;
    if (i < BB*MM*WW) g_z[i] = 0.0f;
    if (i < BB*MM)    g_wsum[i] = 0.0f;
}

// ---------------------------------------------------------------------------
// z[b,m,c] += sum_n w[b,n,m] * h[b,n,c]   (chunked over n, atomics into g_z)
// ---------------------------------------------------------------------------
__global__ __launch_bounds__(256) void k_zacc()
{
    int bx = blockIdx.x;
    int b  = bx >> 8;
    int n0 = (bx & 255) * 64;
    int t  = threadIdx.x;
    __shared__ __align__(8) float shw[8*32];

    ull acc[16];
    #pragma unroll
    for (int i = 0; i < 16; i++) acc[i] = pk2(0.0f, 0.0f);

    for (int nb = 0; nb < 64; nb += 8) {
        int n = n0 + nb + (t >> 5);
        shw[t] = g_w[(b*NN + n)*MM + (t & 31)];
        __syncthreads();
        #pragma unroll
        for (int j = 0; j < 8; j++) {
            float hv = g_h[(b*NN + n0 + nb + j)*WW + t];
            ull hp = pk2(hv, hv);
            const ull* wp = (const ull*)&shw[j*32];
            #pragma unroll
            for (int mp = 0; mp < 16; mp++) ffma2(acc[mp], hp, wp[mp]);
        }
        __syncthreads();
    }
    #pragma unroll
    for (int mp = 0; mp < 16; mp++) {
        float lo, hi; upk2(acc[mp], lo, hi);
        atomicAdd(&g_z[(b*MM + 2*mp    )*WW + t], lo);
        atomicAdd(&g_z[(b*MM + 2*mp + 1)*WW + t], hi);
    }
}

// ---------------------------------------------------------------------------
// small GEMM on 32 tokens: out = in(32x256) @ wt(256 x ncols) + bias
// ---------------------------------------------------------------------------
__global__ __launch_bounds__(256) void k_smallmm(
    const float* __restrict__ wt, const float* __restrict__ bias,
    int ncols, int mode)
{
    int nb = ncols >> 5;
    int b  = blockIdx.x / nb;
    int cb = blockIdx.x % nb;
    int t  = threadIdx.x;
    __shared__ float zs[32*257];

    for (int i = t; i < 32*256; i += 256) {
        int m = i >> 8, c = i & 255;
        float v;
        if (mode == 0) v = g_z[(b*MM + m)*WW + c] / fmaxf(g_wsum[b*MM + m], 1e-8f);
        else           v = g_o[(b*MM + m)*WW + c];
        zs[m*257 + c] = v;
    }
    __syncthreads();

    int r  = t & 31;
    int c0 = cb*32 + (t >> 5)*4;
    float a0 = bias[c0], a1 = bias[c0+1], a2 = bias[c0+2], a3 = bias[c0+3];
    for (int k = 0; k < 256; k++) {
        float zv = zs[r*257 + k];
        const float* wr = &wt[k*ncols + c0];
        a0 = fmaf(zv, wr[0], a0);
        a1 = fmaf(zv, wr[1], a1);
        a2 = fmaf(zv, wr[2], a2);
        a3 = fmaf(zv, wr[3], a3);
    }
    float* outp = (mode == 0) ? &g_qkv[(b*MM + r)*3*WW] : &g_zp[(b*MM + r)*WW];
    outp[c0] = a0; outp[c0+1] = a1; outp[c0+2] = a2; outp[c0+3] = a3;
}

// ---------------------------------------------------------------------------
// attention over M=32 tokens, per (b, head)
// ---------------------------------------------------------------------------
__global__ __launch_bounds__(256) void k_attn()
{
    int b = blockIdx.x >> 3, h = blockIdx.x & 7, t = threadIdx.x;
    __shared__ float qs[32*33], ks[32*33], vs[32*33], ss[32*33];

    for (int i = t; i < 1024; i += 256) {
        int m = i >> 5, d = i & 31;
        int base = (b*MM + m)*3*WW + h*DHH + d;
        qs[m*33 + d] = g_qkv[base];
        ks[m*33 + d] = g_qkv[base + WW];
        vs[m*33 + d] = g_qkv[base + 2*WW];
    }
    __syncthreads();

    int i = t & 31, j0 = (t >> 5)*4;
    float sc[4] = {0,0,0,0};
    #pragma unroll
    for (int d = 0; d < 32; d++) {
        float qv = qs[i*33 + d];
        #pragma unroll
        for (int jj = 0; jj < 4; jj++) sc[jj] = fmaf(qv, ks[(j0+jj)*33 + d], sc[jj]);
    }
    const float scale = 0.17677669529663687f; // 1/sqrt(32)
    #pragma unroll
    for (int jj = 0; jj < 4; jj++) ss[i*33 + j0 + jj] = sc[jj]*scale;
    __syncthreads();

    if (t < 32) {
        float mx = -1e30f;
        for (int j = 0; j < 32; j++) mx = fmaxf(mx, ss[t*33 + j]);
        float se = 0.0f;
        for (int j = 0; j < 32; j++) { float e = expf(ss[t*33 + j] - mx); ss[t*33 + j] = e; se += e; }
        float inv = 1.0f / se;
        for (int j = 0; j < 32; j++) ss[t*33 + j] *= inv;
    }
    __syncthreads();

    int d0 = (t >> 5)*4;
    float oc[4] = {0,0,0,0};
    #pragma unroll
    for (int j = 0; j < 32; j++) {
        float av = ss[i*33 + j];
        #pragma unroll
        for (int dd = 0; dd < 4; dd++) oc[dd] = fmaf(av, vs[j*33 + d0 + dd], oc[dd]);
    }
    #pragma unroll
    for (int dd = 0; dd < 4; dd++) g_o[(b*MM + i)*WW + h*DHH + d0 + dd] = oc[dd];
}

// ---------------------------------------------------------------------------
// scatter back: x[row,:] += sum_m w[row,m] * zp[b,m,:]
// ---------------------------------------------------------------------------
__global__ __launch_bounds__(256) void k_scatter()
{
    int t = threadIdx.x;
    int row0 = blockIdx.x * 16;
    int b = row0 >> 14;
    __shared__ float zps[MM*WW];
    __shared__ float wr[32];

    for (int i = t; i < MM*WW; i += 256) zps[i] = g_zp[b*MM*WW + i];
    __syncthreads();

    for (int r = 0; r < 16; r++) {
        int row = row0 + r;
        if (t < 32) wr[t] = g_w[row*MM + t];
        __syncthreads();
        float acc = g_x[row*WW + t];
        #pragma unroll
        for (int m = 0; m < 32; m++) acc = fmaf(wr[m], zps[m*WW + t], acc);
        g_x[row*WW + t] = acc;
        __syncthreads();
    }
}

// ---------------------------------------------------------------------------
// weight transpose + fp16 convert:  src [K, N] f32  ->  dst [N, K] half
// ---------------------------------------------------------------------------
__global__ __launch_bounds__(256) void k_wt(
    const float* __restrict__ src, int which, int dstoff, int K, int N)
{
    __half* dst = (which ? g_wB2 : g_wB1) + dstoff;
    __shared__ float tile[32][33];
    int bx = blockIdx.x * 32;   // N
    int by = blockIdx.y * 32;   // K
    int tx = threadIdx.x & 31, ty = threadIdx.x >> 5;
    #pragma unroll
    for (int r = ty; r < 32; r += 8) tile[r][tx] = src[(size_t)(by + r)*N + bx + tx];
    __syncthreads();
    #pragma unroll
    for (int r = ty; r < 32; r += 8)
        dst[(size_t)(bx + r)*K + by + tx] = __float2half(tile[tx][r]);
}

// ---------------------------------------------------------------------------
// FP16 tensor-core GEMM (mma.sync.m16n8k16). 128x128 CTA tile, BK=32 halves,
// double-buffered smem, 8 warps @ 64x32 warp tiles.
// MODE 0:  g_u = gelu(g_h @ W1 + bias)       (K=256, Ncols=1024)
// MODE 1:  g_x += g_u @ W2 + bias            (K=1024, Ncols=256)
//
// B is pre-transposed to [N,K] half (g_wB*). smem holds half2 "pair" words;
// k-pairs within each 8-group stored in order [0,4,1,5,2,6,3,7] so each
// thread's fragment (pair cc and cc+4) is one 8-byte LDS. Row stride
// 18 words (72B) — same banking as the proven tf32 kernel.
// ---------------------------------------------------------------------------
__device__ __forceinline__ int pcol(int p){
    return ((p >> 3) << 3) + ((p & 3) << 1) + ((p >> 2) & 1);
}

template<int MODE>
__global__ __launch_bounds__(256, 2) void k_gemm_tc(
    const __half* __restrict__ Bw, const float* __restrict__ bias,
    int K, int Ncols)
{
    const float* __restrict__ A = (MODE == 0) ? g_h : g_u;
    float* __restrict__ C       = (MODE == 0) ? g_u : g_x;

    __shared__ unsigned As[2][128*18];
    __shared__ unsigned Bs[2][128*18];

    int tid  = threadIdx.x;
    int bm0  = blockIdx.y * 128;
    int bn0  = blockIdx.x * 128;
    int lane = tid & 31, warp = tid >> 5;
    int wm = warp >> 2, wn = warp & 3;      // 2 x 4 warp grid
    int r  = lane >> 2, cc = lane & 3;

    float4 aReg[4];
    uint4  bReg[2];

    float acc[4][4][4];
    #pragma unroll
    for (int mi = 0; mi < 4; mi++)
        #pragma unroll
        for (int ni = 0; ni < 4; ni++)
            #pragma unroll
            for (int e = 0; e < 4; e++) acc[mi][ni][e] = 0.0f;

    // ---- stage load to regs: A = 128 rows x 32 floats; B = 128 rows x 32 halves
    #define LOAD_STAGE(k0)                                                         \
        _Pragma("unroll")                                                          \
        for (int i = 0; i < 4; i++) {                                              \
            int idx = tid + 256*i;            /* 0..1023 */                        \
            int ar = idx >> 3, kq = idx & 7;  /* row, float4 index */              \
            aReg[i] = *(const float4*)&A[(size_t)(bm0 + ar)*K + (k0) + kq*4];      \
        }                                                                          \
        _Pragma("unroll")                                                          \
        for (int i = 0; i < 2; i++) {                                              \
            int idx = tid + 256*i;            /* 0..511 */                         \
            int nr = idx >> 2, kq4 = idx & 3; /* row, uint4 (8 halves) index */    \
            bReg[i] = *(const uint4*)&Bw[(size_t)(bn0 + nr)*K + (k0) + kq4*8];     \
        }

    // ---- regs -> smem with fp16 convert + k-pair permute ----
    #define STORE_STAGE(buf)                                                       \
        _Pragma("unroll")                                                          \
        for (int i = 0; i < 4; i++) {                                              \
            int idx = tid + 256*i;                                                 \
            int ar = idx >> 3, kq = idx & 7;                                       \
            As[buf][ar*18 + pcol(2*kq    )] = h2bits(aReg[i].x, aReg[i].y);        \
            As[buf][ar*18 + pcol(2*kq + 1)] = h2bits(aReg[i].z, aReg[i].w);        \
        }                                                                          \
        _Pragma("unroll")                                                          \
        for (int i = 0; i < 2; i++) {                                              \
            int idx = tid + 256*i;                                                 \
            int nr = idx >> 2, kq4 = idx & 3;                                      \
            const unsigned* bw = (const unsigned*)&bReg[i];                        \
            _Pragma("unroll")                                                      \
            for (int e = 0; e < 4; e++)                                            \
                Bs[buf][nr*18 + pcol(4*kq4 + e)] = bw[e];                          \
        }

    LOAD_STAGE(0);
    STORE_STAGE(0);
    __syncthreads();

    int nStages = K >> 5;
    for (int s = 0; s < nStages; s++) {
        if (s + 1 < nStages) { LOAD_STAGE((s+1) << 5); }
        int buf = s & 1;
        #pragma unroll
        for (int ks = 0; ks < 2; ks++) {
            uint2 af[4][2];
            #pragma unroll
            for (int mi = 0; mi < 4; mi++) {
                int mb = wm*64 + mi*16;
                af[mi][0] = *(const uint2*)&As[buf][(mb + r    )*18 + ks*8 + 2*cc];
                af[mi][1] = *(const uint2*)&As[buf][(mb + r + 8)*18 + ks*8 + 2*cc];
            }
            uint2 bf[4];
            #pragma unroll
            for (int ni = 0; ni < 4; ni++) {
                int nb = wn*32 + ni*8 + r;
                bf[ni] = *(const uint2*)&Bs[buf][nb*18 + ks*8 + 2*cc];
            }
            #pragma unroll
            for (int mi = 0; mi < 4; mi++)
                #pragma unroll
                for (int ni = 0; ni < 4; ni++) {
                    asm volatile(
                        "mma.sync.aligned.m16n8k16.row.col.f32.f16.f16.f32 "
                        "{%0,%1,%2,%3}, {%4,%5,%6,%7}, {%8,%9}, {%0,%1,%2,%3};"
                        : "+f"(acc[mi][ni][0]), "+f"(acc[mi][ni][1]),
                          "+f"(acc[mi][ni][2]), "+f"(acc[mi][ni][3])
                        : "r"(af[mi][0].x), "r"(af[mi][1].x),
                          "r"(af[mi][0].y), "r"(af[mi][1].y),
                          "r"(bf[ni].x),    "r"(bf[ni].y));
                }
        }
        if (s + 1 < nStages) { STORE_STAGE((s+1) & 1); }
        __syncthreads();
    }

    // ---- epilogue (same fragment mapping as m16n8k8) ----
    #pragma unroll
    for (int mi = 0; mi < 4; mi++) {
        #pragma unroll
        for (int ni = 0; ni < 4; ni++) {
            int col  = bn0 + wn*32 + ni*8 + 2*cc;
            int row0 = bm0 + wm*64 + mi*16 + r;
            float b0v = bias[col], b1v = bias[col+1];
            float v[4];
            v[0] = acc[mi][ni][0] + b0v;  v[1] = acc[mi][ni][1] + b1v;
            v[2] = acc[mi][ni][2] + b0v;  v[3] = acc[mi][ni][3] + b1v;
            if (MODE == 0) {
                #pragma unroll
                for (int e = 0; e < 4; e++)
                    v[e] = 0.5f * v[e] * (1.0f + erff(v[e] * 0.7071067811865476f));
            } else {
                float2 o0 = *(const float2*)&C[(size_t)row0*Ncols + col];
                float2 o1 = *(const float2*)&C[(size_t)(row0+8)*Ncols + col];
                v[0] += o0.x; v[1] += o0.y; v[2] += o1.x; v[3] += o1.y;
            }
            *(float2*)&C[(size_t)row0*Ncols + col]     = make_float2(v[0], v[1]);
            *(float2*)&C[(size_t)(row0+8)*Ncols + col] = make_float2(v[2], v[3]);
        }
    }
}

// ---------------------------------------------------------------------------
// final projection: out = x @ proj_w(256,4) + proj_b
// ---------------------------------------------------------------------------
__global__ __launch_bounds__(256) void k_proj(
    const float* __restrict__ pw, const float* __restrict__ pb,
    float* __restrict__ out)
{
    int t = threadIdx.x;
    int warp = t >> 5, lane = t & 31;
    int row = blockIdx.x*8 + warp;
    float a[4] = {0,0,0,0};
    for (int k = lane; k < 256; k += 32) {
        float xv = g_x[row*WW + k];
        #pragma unroll
        for (int c = 0; c < 4; c++) a[c] = fmaf(xv, pw[k*4 + c], a[c]);
    }
    #pragma unroll
    for (int c = 0; c < 4; c++)
        #pragma unroll
        for (int o = 16; o; o >>= 1) a[c] += __shfl_xor_sync(0xffffffffu, a[c], o);
    if (lane < 4) out[row*4 + lane] = a[lane] + pb[lane];
}

// ---------------------------------------------------------------------------
extern "C" void kernel_launch(void* const* d_in, const int* in_sizes, int n_in,
                              void* d_out, int out_size)
{
    const float* feat  = (const float*)d_in[0];
    const float* coord = (const float*)d_in[1];
    const float* tn    = (const float*)d_in[2];
    const float* ew    = (const float*)d_in[3];
    const float* eb    = (const float*)d_in[4];
    const float* ln1g  = (const float*)d_in[5];
    const float* ln1b  = (const float*)d_in[6];
    const float* sw    = (const float*)d_in[7];
    const float* sb    = (const float*)d_in[8];
    const float* qkvw  = (const float*)d_in[9];
    const float* qkvb  = (const float*)d_in[10];
    const float* outw  = (const float*)d_in[11];
    const float* outb  = (const float*)d_in[12];
    const float* ln2g  = (const float*)d_in[13];
    const float* ln2b  = (const float*)d_in[14];
    const float* f1w   = (const float*)d_in[15];
    const float* f1b   = (const float*)d_in[16];
    const float* f2w   = (const float*)d_in[17];
    const float* f2b   = (const float*)d_in[18];
    const float* pw    = (const float*)d_in[19];
    const float* pb    = (const float*)d_in[20];

    // one-time weight transposes (fp16, [N,K])
    for (int l = 0; l < LL; l++) {
        k_wt<<<dim3(FFD/32, WW/32), 256>>>(f1w + (size_t)l*WW*FFD, 0, l*FFD*WW, WW, FFD);
        k_wt<<<dim3(WW/32, FFD/32), 256>>>(f2w + (size_t)l*FFD*WW, 1, l*WW*FFD, FFD, WW);
    }

    k_embed<<<BN, 256>>>(feat, coord, tn, ew, eb);

    // device-pointer bases for the fp16 weight arrays
    __half* wB1base; cudaGetSymbolAddress((void**)&wB1base, g_wB1);
    __half* wB2base; cudaGetSymbolAddress((void**)&wB2base, g_wB2);

    for (int l = 0; l < LL; l++) {
        k_zero<<<128, 256>>>();
        k_ln_slice<<<BN, 256>>>(ln1g + l*WW, ln1b + l*WW,
                                sw + (size_t)l*WW*MM, sb + l*MM);
        k_zacc<<<1024, 256>>>();
        k_smallmm<<<BB*24, 256>>>(qkvw + (size_t)l*WW*3*WW, qkvb + l*3*WW, 3*WW, 0);
        k_attn<<<BB*HH, 256>>>();
        k_smallmm<<<BB*8, 256>>>(outw + (size_t)l*WW*WW, outb + l*WW, WW, 1);
        k_scatter<<<BN/16, 256>>>();
        k_ln<<<BN, 256>>>(ln2g + l*WW, ln2b + l*WW);
        {
            dim3 g1(FFD/128, BN/128);   // 8 x 512
            k_gemm_tc<0><<<g1, 256>>>(wB1base + (size_t)l*FFD*WW, f1b + l*FFD, WW, FFD);
            dim3 g2(WW/128, BN/128);    // 2 x 512
            k_gemm_tc<1><<<g2, 256>>>(wB2base + (size_t)l*WW*FFD, f2b + l*WW, FFD, WW);
        }
    }

    k_proj<<<BN/8, 256>>>(pw, pb, (float*)d_out);
}

// round 8
// speedup vs baseline: 2.3495x; 1.0591x over previous
#include <cuda_runtime.h>
#include <cuda_fp16.h>
#include <math.h>
#include <stdint.h>

// Problem constants
#define BB   4
#define NN   16384
#define WW   256
#define MM   32
#define HH   8
#define DHH  32
#define FFD  1024
#define LL   8
#define BN   (BB*NN)

// Scratch (device globals — allocation-free rule)
__device__ float  g_x[BN*WW];        // residual stream (f32)
__device__ float  g_h[BN*WW];        // LN1 output (f32, feeds zacc/slice)
__device__ __half g_hh[BN*WW];       // LN2 output (fp16, feeds FFN GEMM1)
__device__ float  g_w[BN*MM];        // slice weights
__device__ __half g_u[BN*FFD];       // FFN hidden (fp16)
__device__ float  g_z[BB*MM*WW];
__device__ float  g_qkv[BB*MM*3*WW];
__device__ float  g_o[BB*MM*WW];
__device__ float  g_zp[BB*MM*WW];
__device__ float  g_wsum[BB*MM];
// transposed fp16 weights: [N, K] K-major
__device__ __half g_wB1[LL*FFD*WW];   // ffn1^T : [1024, 256] per layer
__device__ __half g_wB2[LL*WW*FFD];   // ffn2^T : [256, 1024] per layer

typedef unsigned long long ull;

__device__ __forceinline__ void ffma2(ull& d, ull a, ull b){
    asm("fma.rn.f32x2 %0, %1, %2, %0;" : "+l"(d) : "l"(a), "l"(b));
}
__device__ __forceinline__ ull pk2(float lo, float hi){
    ull r; asm("mov.b64 %0, {%1, %2};" : "=l"(r) : "f"(lo), "f"(hi)); return r;
}
__device__ __forceinline__ void upk2(ull v, float& lo, float& hi){
    asm("mov.b64 {%0, %1}, %2;" : "=f"(lo), "=f"(hi) : "l"(v));
}

// ---------------------------------------------------------------------------
// Embedding: x = concat(feat[4], coord[3], temb[8]) @ embed_w(15,256) + b
// ---------------------------------------------------------------------------
__global__ __launch_bounds__(256) void k_embed(
    const float* __restrict__ feat, const float* __restrict__ coord,
    const float* __restrict__ tn,   const float* __restrict__ ew,
    const float* __restrict__ eb)
{
    int row = blockIdx.x;          // 0..BN-1
    int b   = row >> 14;           // N = 16384
    int t   = threadIdx.x;
    __shared__ float in15[16];
    if (t < 4) {
        in15[t] = feat[row*4 + t];
    } else if (t < 7) {
        in15[t] = coord[row*3 + (t-4)];
    } else if (t < 15) {
        int i = (t - 7) & 3;
        float omega = (float)exp(-(double)i * log(1000.0) / 4.0);
        float ang   = omega * (tn[b] * 1000.0f);
        in15[t] = (t < 11) ? sinf(ang) : cosf(ang);
    }
    __syncthreads();
    float acc = eb[t];
    #pragma unroll
    for (int j = 0; j < 15; j++) acc = fmaf(in15[j], ew[j*WW + t], acc);
    g_x[row*WW + t] = acc;
}

// ---------------------------------------------------------------------------
// LayerNorm helper (block of 256 threads = one row; value passed in)
// ---------------------------------------------------------------------------
__device__ __forceinline__ float ln_val(float xv, int t,
    const float* __restrict__ gam, const float* __restrict__ bet, float* red)
{
    float s = xv;
    #pragma unroll
    for (int o = 16; o; o >>= 1) s += __shfl_xor_sync(0xffffffffu, s, o);
    if ((t & 31) == 0) red[t >> 5] = s;
    __syncthreads();
    if (t < 8) {
        float r = red[t];
        #pragma unroll
        for (int o = 4; o; o >>= 1) r += __shfl_xor_sync(0xffu, r, o);
        if (t == 0) red[8] = r;
    }
    __syncthreads();
    float mean = red[8] * (1.0f/WW);
    float d = xv - mean;
    float s2 = d*d;
    #pragma unroll
    for (int o = 16; o; o >>= 1) s2 += __shfl_xor_sync(0xffffffffu, s2, o);
    if ((t & 31) == 0) red[t >> 5] = s2;
    __syncthreads();
    if (t < 8) {
        float r = red[t];
        #pragma unroll
        for (int o = 4; o; o >>= 1) r += __shfl_xor_sync(0xffu, r, o);
        if (t == 0) red[9] = r;
    }
    __syncthreads();
    float var = red[9] * (1.0f/WW);
    return d * rsqrtf(var + 1e-5f) * gam[t] + bet[t];
}

// LN1 + slice logits + softmax + wsum atomic
__global__ __launch_bounds__(256) void k_ln_slice(
    const float* __restrict__ gam, const float* __restrict__ bet,
    const float* __restrict__ sw,  const float* __restrict__ sb)
{
    int row = blockIdx.x;
    int b   = row >> 14;
    int t   = threadIdx.x;
    __shared__ float red[16];
    __shared__ float sh[WW];
    __shared__ float part[256];

    float hv = ln_val(g_x[row*WW + t], t, gam, bet, red);
    g_h[row*WW + t] = hv;
    sh[t] = hv;
    __syncthreads();

    int m = t & 31, kb = t >> 5;
    float p = 0.0f;
    #pragma unroll
    for (int k = 0; k < 32; k++)
        p = fmaf(sh[kb*32 + k], sw[(kb*32 + k)*MM + m], p);
    part[t] = p;
    __syncthreads();

    if (t < 32) {
        float lg = sb[t];
        #pragma unroll
        for (int kb2 = 0; kb2 < 8; kb2++) lg += part[kb2*32 + t];
        float mx = lg;
        #pragma unroll
        for (int o = 16; o; o >>= 1) mx = fmaxf(mx, __shfl_xor_sync(0xffffffffu, mx, o));
        float e = expf(lg - mx);
        float se = e;
        #pragma unroll
        for (int o = 16; o; o >>= 1) se += __shfl_xor_sync(0xffffffffu, se, o);
        float wv = e / se;
        g_w[row*MM + t] = wv;
        atomicAdd(&g_wsum[b*MM + t], wv);
    }
}

// zero z + wsum
__global__ void k_zero()
{
    int i = blockIdx.x*256 + threadIdx.x;
    if (i < BB*MM*WW) g_z[i] = 0.0f;
    if (i < BB*MM)    g_wsum[i] = 0.0f;
}

// ---------------------------------------------------------------------------
// z[b,m,c] += sum_n w[b,n,m] * h[b,n,c]   (chunked over n, atomics into g_z)
// ---------------------------------------------------------------------------
__global__ __launch_bounds__(256) void k_zacc()
{
    int bx = blockIdx.x;
    int b  = bx >> 8;
    int n0 = (bx & 255) * 64;
    int t  = threadIdx.x;
    __shared__ __align__(8) float shw[8*32];

    ull acc[16];
    #pragma unroll
    for (int i = 0; i < 16; i++) acc[i] = pk2(0.0f, 0.0f);

    for (int nb = 0; nb < 64; nb += 8) {
        int n = n0 + nb + (t >> 5);
        shw[t] = g_w[(b*NN + n)*MM + (t & 31)];
        __syncthreads();
        #pragma unroll
        for (int j = 0; j < 8; j++) {
            float hv = g_h[(b*NN + n0 + nb + j)*WW + t];
            ull hp = pk2(hv, hv);
            const ull* wp = (const ull*)&shw[j*32];
            #pragma unroll
            for (int mp = 0; mp < 16; mp++) ffma2(acc[mp], hp, wp[mp]);
        }
        __syncthreads();
    }
    #pragma unroll
    for (int mp = 0; mp < 16; mp++) {
        float lo, hi; upk2(acc[mp], lo, hi);
        atomicAdd(&g_z[(b*MM + 2*mp    )*WW + t], lo);
        atomicAdd(&g_z[(b*MM + 2*mp + 1)*WW + t], hi);
    }
}

// ---------------------------------------------------------------------------
// small GEMM on 32 tokens: out = in(32x256) @ wt(256 x ncols) + bias
// ---------------------------------------------------------------------------
__global__ __launch_bounds__(256) void k_smallmm(
    const float* __restrict__ wt, const float* __restrict__ bias,
    int ncols, int mode)
{
    int nb = ncols >> 5;
    int b  = blockIdx.x / nb;
    int cb = blockIdx.x % nb;
    int t  = threadIdx.x;
    __shared__ float zs[32*257];

    for (int i = t; i < 32*256; i += 256) {
        int m = i >> 8, c = i & 255;
        float v;
        if (mode == 0) v = g_z[(b*MM + m)*WW + c] / fmaxf(g_wsum[b*MM + m], 1e-8f);
        else           v = g_o[(b*MM + m)*WW + c];
        zs[m*257 + c] = v;
    }
    __syncthreads();

    int r  = t & 31;
    int c0 = cb*32 + (t >> 5)*4;
    float a0 = bias[c0], a1 = bias[c0+1], a2 = bias[c0+2], a3 = bias[c0+3];
    for (int k = 0; k < 256; k++) {
        float zv = zs[r*257 + k];
        const float* wr = &wt[k*ncols + c0];
        a0 = fmaf(zv, wr[0], a0);
        a1 = fmaf(zv, wr[1], a1);
        a2 = fmaf(zv, wr[2], a2);
        a3 = fmaf(zv, wr[3], a3);
    }
    float* outp = (mode == 0) ? &g_qkv[(b*MM + r)*3*WW] : &g_zp[(b*MM + r)*WW];
    outp[c0] = a0; outp[c0+1] = a1; outp[c0+2] = a2; outp[c0+3] = a3;
}

// ---------------------------------------------------------------------------
// attention over M=32 tokens, per (b, head)
// ---------------------------------------------------------------------------
__global__ __launch_bounds__(256) void k_attn()
{
    int b = blockIdx.x >> 3, h = blockIdx.x & 7, t = threadIdx.x;
    __shared__ float qs[32*33], ks[32*33], vs[32*33], ss[32*33];

    for (int i = t; i < 1024; i += 256) {
        int m = i >> 5, d = i & 31;
        int base = (b*MM + m)*3*WW + h*DHH + d;
        qs[m*33 + d] = g_qkv[base];
        ks[m*33 + d] = g_qkv[base + WW];
        vs[m*33 + d] = g_qkv[base + 2*WW];
    }
    __syncthreads();

    int i = t & 31, j0 = (t >> 5)*4;
    float sc[4] = {0,0,0,0};
    #pragma unroll
    for (int d = 0; d < 32; d++) {
        float qv = qs[i*33 + d];
        #pragma unroll
        for (int jj = 0; jj < 4; jj++) sc[jj] = fmaf(qv, ks[(j0+jj)*33 + d], sc[jj]);
    }
    const float scale = 0.17677669529663687f; // 1/sqrt(32)
    #pragma unroll
    for (int jj = 0; jj < 4; jj++) ss[i*33 + j0 + jj] = sc[jj]*scale;
    __syncthreads();

    if (t < 32) {
        float mx = -1e30f;
        for (int j = 0; j < 32; j++) mx = fmaxf(mx, ss[t*33 + j]);
        float se = 0.0f;
        for (int j = 0; j < 32; j++) { float e = expf(ss[t*33 + j] - mx); ss[t*33 + j] = e; se += e; }
        float inv = 1.0f / se;
        for (int j = 0; j < 32; j++) ss[t*33 + j] *= inv;
    }
    __syncthreads();

    int d0 = (t >> 5)*4;
    float oc[4] = {0,0,0,0};
    #pragma unroll
    for (int j = 0; j < 32; j++) {
        float av = ss[i*33 + j];
        #pragma unroll
        for (int dd = 0; dd < 4; dd++) oc[dd] = fmaf(av, vs[j*33 + d0 + dd], oc[dd]);
    }
    #pragma unroll
    for (int dd = 0; dd < 4; dd++) g_o[(b*MM + i)*WW + h*DHH + d0 + dd] = oc[dd];
}

// ---------------------------------------------------------------------------
// fused scatter + LN2:
//   x[row,:] += sum_m w[row,m] * zp[b,m,:]   (writes g_x f32)
//   g_hh[row,:] = fp16( LN(x[row,:]) )       (feeds FFN GEMM1)
// ---------------------------------------------------------------------------
__global__ __launch_bounds__(256) void k_scatter_ln(
    const float* __restrict__ gam, const float* __restrict__ bet)
{
    int t = threadIdx.x;
    int row0 = blockIdx.x * 16;
    int b = row0 >> 14;
    __shared__ float zps[MM*WW];
    __shared__ float wr[32];
    __shared__ float red[16];

    for (int i = t; i < MM*WW; i += 256) zps[i] = g_zp[b*MM*WW + i];
    __syncthreads();

    for (int r = 0; r < 16; r++) {
        int row = row0 + r;
        if (t < 32) wr[t] = g_w[row*MM + t];
        __syncthreads();
        float acc = g_x[row*WW + t];
        #pragma unroll
        for (int m = 0; m < 32; m++) acc = fmaf(wr[m], zps[m*WW + t], acc);
        g_x[row*WW + t] = acc;
        // LN on the fresh value (reduction has its own syncs)
        float hv = ln_val(acc, t, gam, bet, red);
        g_hh[row*WW + t] = __float2half(hv);
        __syncthreads();
    }
}

// ---------------------------------------------------------------------------
// weight transpose + fp16 convert:  src [K, N] f32  ->  dst [N, K] half
// ---------------------------------------------------------------------------
__global__ __launch_bounds__(256) void k_wt(
    const float* __restrict__ src, int which, int dstoff, int K, int N)
{
    __half* dst = (which ? g_wB2 : g_wB1) + dstoff;
    __shared__ float tile[32][33];
    int bx = blockIdx.x * 32;   // N
    int by = blockIdx.y * 32;   // K
    int tx = threadIdx.x & 31, ty = threadIdx.x >> 5;
    #pragma unroll
    for (int r = ty; r < 32; r += 8) tile[r][tx] = src[(size_t)(by + r)*N + bx + tx];
    __syncthreads();
    #pragma unroll
    for (int r = ty; r < 32; r += 8)
        dst[(size_t)(bx + r)*K + by + tx] = __float2half(tile[tx][r]);
}

// ---------------------------------------------------------------------------
// FP16 tensor-core GEMM (mma.sync.m16n8k16). 128x128 CTA tile, BK=32 halves,
// double-buffered smem, 8 warps @ 64x32 warp tiles. A and B are both fp16
// [rows, K] K-major in gmem (A = activations, B = pre-transposed weights).
// MODE 0:  g_u  = fp16(gelu(g_hh @ W1 + bias))   (K=256, Ncols=1024)
// MODE 1:  g_x += g_u @ W2 + bias                (K=1024, Ncols=256)
//
// smem: half2 "pair" words; k-pairs within each 8-group stored in order
// [0,4,1,5,2,6,3,7] so each thread's fragment (pair cc, cc+4) is one 8B LDS.
// Row stride 18 words (72B).
// ---------------------------------------------------------------------------
__device__ __forceinline__ int pcol(int p){
    return ((p >> 3) << 3) + ((p & 3) << 1) + ((p >> 2) & 1);
}

template<int MODE>
__global__ __launch_bounds__(256, 2) void k_gemm_tc(
    const __half* __restrict__ Bw, const float* __restrict__ bias,
    int K, int Ncols)
{
    const __half* __restrict__ A = (MODE == 0) ? g_hh : g_u;

    __shared__ unsigned As[2][128*18];
    __shared__ unsigned Bs[2][128*18];

    int tid  = threadIdx.x;
    int bm0  = blockIdx.y * 128;
    int bn0  = blockIdx.x * 128;
    int lane = tid & 31, warp = tid >> 5;
    int wm = warp >> 2, wn = warp & 3;      // 2 x 4 warp grid
    int r  = lane >> 2, cc = lane & 3;

    uint4 aR[2], bR[2];

    float acc[4][4][4];
    #pragma unroll
    for (int mi = 0; mi < 4; mi++)
        #pragma unroll
        for (int ni = 0; ni < 4; ni++)
            #pragma unroll
            for (int e = 0; e < 4; e++) acc[mi][ni][e] = 0.0f;

    // ---- stage load to regs: each operand 128 rows x 32 halves (8KB) ----
    #define LOAD_STAGE(k0)                                                         \
        _Pragma("unroll")                                                          \
        for (int i = 0; i < 2; i++) {                                              \
            int idx = tid + 256*i;            /* 0..511 */                         \
            int rr = idx >> 2, kq4 = idx & 3; /* row, uint4 (8 halves) index */    \
            aR[i] = *(const uint4*)&A[(size_t)(bm0 + rr)*K + (k0) + kq4*8];        \
            bR[i] = *(const uint4*)&Bw[(size_t)(bn0 + rr)*K + (k0) + kq4*8];       \
        }

    // ---- regs -> smem with k-pair permute ----
    #define STORE_STAGE(buf)                                                       \
        _Pragma("unroll")                                                          \
        for (int i = 0; i < 2; i++) {                                              \
            int idx = tid + 256*i;                                                 \
            int rr = idx >> 2, kq4 = idx & 3;                                      \
            const unsigned* aw = (const unsigned*)&aR[i];                          \
            const unsigned* bw = (const unsigned*)&bR[i];                          \
            _Pragma("unroll")                                                      \
            for (int e = 0; e < 4; e++) {                                          \
                int pc = pcol(4*kq4 + e);                                          \
                As[buf][rr*18 + pc] = aw[e];                                       \
                Bs[buf][rr*18 + pc] = bw[e];                                       \
            }                                                                      \
        }

    LOAD_STAGE(0);
    STORE_STAGE(0);
    __syncthreads();

    int nStages = K >> 5;
    for (int s = 0; s < nStages; s++) {
        if (s + 1 < nStages) { LOAD_STAGE((s+1) << 5); }
        int buf = s & 1;
        #pragma unroll
        for (int ks = 0; ks < 2; ks++) {
            uint2 af[4][2];
            #pragma unroll
            for (int mi = 0; mi < 4; mi++) {
                int mb = wm*64 + mi*16;
                af[mi][0] = *(const uint2*)&As[buf][(mb + r    )*18 + ks*8 + 2*cc];
                af[mi][1] = *(const uint2*)&As[buf][(mb + r + 8)*18 + ks*8 + 2*cc];
            }
            uint2 bf[4];
            #pragma unroll
            for (int ni = 0; ni < 4; ni++) {
                int nb = wn*32 + ni*8 + r;
                bf[ni] = *(const uint2*)&Bs[buf][nb*18 + ks*8 + 2*cc];
            }
            #pragma unroll
            for (int mi = 0; mi < 4; mi++)
                #pragma unroll
                for (int ni = 0; ni < 4; ni++) {
                    asm volatile(
                        "mma.sync.aligned.m16n8k16.row.col.f32.f16.f16.f32 "
                        "{%0,%1,%2,%3}, {%4,%5,%6,%7}, {%8,%9}, {%0,%1,%2,%3};"
                        : "+f"(acc[mi][ni][0]), "+f"(acc[mi][ni][1]),
                          "+f"(acc[mi][ni][2]), "+f"(acc[mi][ni][3])
                        : "r"(af[mi][0].x), "r"(af[mi][1].x),
                          "r"(af[mi][0].y), "r"(af[mi][1].y),
                          "r"(bf[ni].x),    "r"(bf[ni].y));
                }
        }
        if (s + 1 < nStages) { STORE_STAGE((s+1) & 1); }
        __syncthreads();
    }

    // ---- epilogue ----
    #pragma unroll
    for (int mi = 0; mi < 4; mi++) {
        #pragma unroll
        for (int ni = 0; ni < 4; ni++) {
            int col  = bn0 + wn*32 + ni*8 + 2*cc;
            int row0 = bm0 + wm*64 + mi*16 + r;
            float b0v = bias[col], b1v = bias[col+1];
            float v[4];
            v[0] = acc[mi][ni][0] + b0v;  v[1] = acc[mi][ni][1] + b1v;
            v[2] = acc[mi][ni][2] + b0v;  v[3] = acc[mi][ni][3] + b1v;
            if (MODE == 0) {
                #pragma unroll
                for (int e = 0; e < 4; e++)
                    v[e] = 0.5f * v[e] * (1.0f + erff(v[e] * 0.7071067811865476f));
                *(__half2*)&g_u[(size_t)row0*Ncols + col]     = __floats2half2_rn(v[0], v[1]);
                *(__half2*)&g_u[(size_t)(row0+8)*Ncols + col] = __floats2half2_rn(v[2], v[3]);
            } else {
                float2 o0 = *(const float2*)&g_x[(size_t)row0*Ncols + col];
                float2 o1 = *(const float2*)&g_x[(size_t)(row0+8)*Ncols + col];
                v[0] += o0.x; v[1] += o0.y; v[2] += o1.x; v[3] += o1.y;
                *(float2*)&g_x[(size_t)row0*Ncols + col]     = make_float2(v[0], v[1]);
                *(float2*)&g_x[(size_t)(row0+8)*Ncols + col] = make_float2(v[2], v[3]);
            }
        }
    }
}

// ---------------------------------------------------------------------------
// final projection: out = x @ proj_w(256,4) + proj_b
// ---------------------------------------------------------------------------
__global__ __launch_bounds__(256) void k_proj(
    const float* __restrict__ pw, const float* __restrict__ pb,
    float* __restrict__ out)
{
    int t = threadIdx.x;
    int warp = t >> 5, lane = t & 31;
    int row = blockIdx.x*8 + warp;
    float a[4] = {0,0,0,0};
    for (int k = lane; k < 256; k += 32) {
        float xv = g_x[row*WW + k];
        #pragma unroll
        for (int c = 0; c < 4; c++) a[c] = fmaf(xv, pw[k*4 + c], a[c]);
    }
    #pragma unroll
    for (int c = 0; c < 4; c++)
        #pragma unroll
        for (int o = 16; o; o >>= 1) a[c] += __shfl_xor_sync(0xffffffffu, a[c], o);
    if (lane < 4) out[row*4 + lane] = a[lane] + pb[lane];
}

// ---------------------------------------------------------------------------
extern "C" void kernel_launch(void* const* d_in, const int* in_sizes, int n_in,
                              void* d_out, int out_size)
{
    const float* feat  = (const float*)d_in[0];
    const float* coord = (const float*)d_in[1];
    const float* tn    = (const float*)d_in[2];
    const float* ew    = (const float*)d_in[3];
    const float* eb    = (const float*)d_in[4];
    const float* ln1g  = (const float*)d_in[5];
    const float* ln1b  = (const float*)d_in[6];
    const float* sw    = (const float*)d_in[7];
    const float* sb    = (const float*)d_in[8];
    const float* qkvw  = (const float*)d_in[9];
    const float* qkvb  = (const float*)d_in[10];
    const float* outw  = (const float*)d_in[11];
    const float* outb  = (const float*)d_in[12];
    const float* ln2g  = (const float*)d_in[13];
    const float* ln2b  = (const float*)d_in[14];
    const float* f1w   = (const float*)d_in[15];
    const float* f1b   = (const float*)d_in[16];
    const float* f2w   = (const float*)d_in[17];
    const float* f2b   = (const float*)d_in[18];
    const float* pw    = (const float*)d_in[19];
    const float* pb    = (const float*)d_in[20];

    // one-time weight transposes (fp16, [N,K])
    for (int l = 0; l < LL; l++) {
        k_wt<<<dim3(FFD/32, WW/32), 256>>>(f1w + (size_t)l*WW*FFD, 0, l*FFD*WW, WW, FFD);
        k_wt<<<dim3(WW/32, FFD/32), 256>>>(f2w + (size_t)l*FFD*WW, 1, l*WW*FFD, FFD, WW);
    }

    k_embed<<<BN, 256>>>(feat, coord, tn, ew, eb);

    // device-pointer bases for the fp16 weight arrays
    __half* wB1base; cudaGetSymbolAddress((void**)&wB1base, g_wB1);
    __half* wB2base; cudaGetSymbolAddress((void**)&wB2base, g_wB2);

    for (int l = 0; l < LL; l++) {
        k_zero<<<128, 256>>>();
        k_ln_slice<<<BN, 256>>>(ln1g + l*WW, ln1b + l*WW,
                                sw + (size_t)l*WW*MM, sb + l*MM);
        k_zacc<<<1024, 256>>>();
        k_smallmm<<<BB*24, 256>>>(qkvw + (size_t)l*WW*3*WW, qkvb + l*3*WW, 3*WW, 0);
        k_attn<<<BB*HH, 256>>>();
        k_smallmm<<<BB*8, 256>>>(outw + (size_t)l*WW*WW, outb + l*WW, WW, 1);
        k_scatter_ln<<<BN/16, 256>>>(ln2g + l*WW, ln2b + l*WW);
        {
            dim3 g1(FFD/128, BN/128);   // 8 x 512
            k_gemm_tc<0><<<g1, 256>>>(wB1base + (size_t)l*FFD*WW, f1b + l*FFD, WW, FFD);
            dim3 g2(WW/128, BN/128);    // 2 x 512
            k_gemm_tc<1><<<g2, 256>>>(wB2base + (size_t)l*WW*FFD, f2b + l*WW, FFD, WW);
        }
    }

    k_proj<<<BN/8, 256>>>(pw, pb, (float*)d_out);
}